// round 1
// baseline (speedup 1.0000x reference)
#include <cuda_runtime.h>
#include <cuda_fp16.h>
#include <cstdint>
#include <cstddef>

#define TOKENS 8192
#define KDIM   4096
#define NDIM   4096
#define NGROUPS 32   // 4096 / 128

// fp16 scratch in device globals (allocation-free rule)
__device__ uint4 g_Xh4[(size_t)TOKENS * KDIM / 8];  // x as half
__device__ uint4 g_Wh4[(size_t)NDIM   * KDIM / 8];  // W as half (unscaled int4 values)

// ---------------------------------------------------------------------------
// x: fp32 -> fp16   (8 floats / thread)
// ---------------------------------------------------------------------------
__global__ void convert_x_kernel(const float* __restrict__ x) {
    size_t idx = (size_t)blockIdx.x * blockDim.x + threadIdx.x;
    const float4* xv = (const float4*)x;
    float4 v0 = xv[2 * idx];
    float4 v1 = xv[2 * idx + 1];
    __half2 h0 = __floats2half2_rn(v0.x, v0.y);
    __half2 h1 = __floats2half2_rn(v0.z, v0.w);
    __half2 h2 = __floats2half2_rn(v1.x, v1.y);
    __half2 h3 = __floats2half2_rn(v1.z, v1.w);
    uint4 o;
    o.x = *reinterpret_cast<unsigned*>(&h0);
    o.y = *reinterpret_cast<unsigned*>(&h1);
    o.z = *reinterpret_cast<unsigned*>(&h2);
    o.w = *reinterpret_cast<unsigned*>(&h3);
    g_Xh4[idx] = o;
}

// ---------------------------------------------------------------------------
// W: packed int4 (one byte per int32) -> fp16 integer values (-8..7), NO scale
// low nibble -> even k, high nibble -> odd k
// 4 packed int32 -> 8 halves per thread
// ---------------------------------------------------------------------------
__global__ void dequant_w_kernel(const int* __restrict__ wp) {
    size_t idx = (size_t)blockIdx.x * blockDim.x + threadIdx.x;
    int4 p = ((const int4*)wp)[idx];
    __align__(16) __half h[8];
    h[0] = __int2half_rn((p.x & 15) - 8);
    h[1] = __int2half_rn(((p.x >> 4) & 15) - 8);
    h[2] = __int2half_rn((p.y & 15) - 8);
    h[3] = __int2half_rn(((p.y >> 4) & 15) - 8);
    h[4] = __int2half_rn((p.z & 15) - 8);
    h[5] = __int2half_rn(((p.z >> 4) & 15) - 8);
    h[6] = __int2half_rn((p.w & 15) - 8);
    h[7] = __int2half_rn(((p.w >> 4) & 15) - 8);
    g_Wh4[idx] = *reinterpret_cast<uint4*>(h);
}

// ---------------------------------------------------------------------------
// GEMM: out[M,N] = sum_g scale[n,g] * (Xh[m, g*128:(g+1)*128] . Wh[n, ...])
// Block tile 128x128x32, 8 warps (2 M x 4 N), warp tile 64x32,
// mma.sync.m16n8k16 fp16 -> fp32, cp.async double buffer,
// group-scale epilogue every 4 k-tiles (group = 128 = 4 * BK).
// ---------------------------------------------------------------------------
#define BM 128
#define BN 128
#define BK 32
#define SAS 40   // shared row stride in halves (32 + 8 pad, keeps 16B alignment)

#define CP16(dst, src) asm volatile("cp.async.cg.shared.global [%0], [%1], 16;" :: "r"(dst), "l"(src))

__global__ void __launch_bounds__(256, 1)
gemm_q4_kernel(const float* __restrict__ scales, float* __restrict__ out) {
    __shared__ __half As[2][BM * SAS];
    __shared__ __half Bs[2][BN * SAS];

    const int tid  = threadIdx.x;
    const int warp = tid >> 5;
    const int lane = tid & 31;
    const int wm = warp >> 2;      // 0..1  -> 64 rows each
    const int wn = warp & 3;       // 0..3  -> 32 cols each
    const int g  = lane >> 2;      // 0..7
    const int tg = lane & 3;       // 0..3

    const int bm = blockIdx.y * BM;
    const int bn = blockIdx.x * BN;

    const __half* __restrict__ Xh = (const __half*)g_Xh4;
    const __half* __restrict__ Wh = (const __half*)g_Wh4;

    float accM[4][4][4];   // master (scaled) accumulators
    float accG[4][4][4];   // per-group accumulators
#pragma unroll
    for (int i = 0; i < 4; i++)
#pragma unroll
        for (int j = 0; j < 4; j++)
#pragma unroll
            for (int r = 0; r < 4; r++) { accM[i][j][r] = 0.f; accG[i][j][r] = 0.f; }

    auto load_tile = [&](int buf, int kt) {
        const int k0 = kt * BK;
#pragma unroll
        for (int i = 0; i < 2; ++i) {
            int c   = tid + i * 256;      // 512 chunks of 16B per (A or B) tile
            int row = c >> 2;
            int cc  = (c & 3) << 3;       // half offset within row
            unsigned sa = (unsigned)__cvta_generic_to_shared(&As[buf][row * SAS + cc]);
            CP16(sa, Xh + (size_t)(bm + row) * KDIM + k0 + cc);
            unsigned sb = (unsigned)__cvta_generic_to_shared(&Bs[buf][row * SAS + cc]);
            CP16(sb, Wh + (size_t)(bn + row) * KDIM + k0 + cc);
        }
        asm volatile("cp.async.commit_group;");
    };

    load_tile(0, 0);

    const int NKT = KDIM / BK;  // 128
    int buf = 0;
#pragma unroll 1
    for (int kt = 0; kt < NKT; ++kt) {
        asm volatile("cp.async.wait_group 0;");
        __syncthreads();
        if (kt + 1 < NKT) load_tile(buf ^ 1, kt + 1);

        // compute on current buffer: two k16 slabs
#pragma unroll
        for (int kk = 0; kk < 2; ++kk) {
            const int k0 = kk * 16;
            unsigned a[4][4];
#pragma unroll
            for (int mt = 0; mt < 4; ++mt) {
                const int rb = wm * 64 + mt * 16;
                a[mt][0] = *(const unsigned*)&As[buf][(rb + g)     * SAS + k0 + tg * 2];
                a[mt][1] = *(const unsigned*)&As[buf][(rb + g + 8) * SAS + k0 + tg * 2];
                a[mt][2] = *(const unsigned*)&As[buf][(rb + g)     * SAS + k0 + tg * 2 + 8];
                a[mt][3] = *(const unsigned*)&As[buf][(rb + g + 8) * SAS + k0 + tg * 2 + 8];
            }
            unsigned b[4][2];
#pragma unroll
            for (int nt = 0; nt < 4; ++nt) {
                const int nb = wn * 32 + nt * 8 + g;
                b[nt][0] = *(const unsigned*)&Bs[buf][nb * SAS + k0 + tg * 2];
                b[nt][1] = *(const unsigned*)&Bs[buf][nb * SAS + k0 + tg * 2 + 8];
            }
#pragma unroll
            for (int mt = 0; mt < 4; ++mt)
#pragma unroll
                for (int nt = 0; nt < 4; ++nt) {
                    asm volatile(
                        "mma.sync.aligned.m16n8k16.row.col.f32.f16.f16.f32 "
                        "{%0,%1,%2,%3}, {%4,%5,%6,%7}, {%8,%9}, {%0,%1,%2,%3};"
                        : "+f"(accG[mt][nt][0]), "+f"(accG[mt][nt][1]),
                          "+f"(accG[mt][nt][2]), "+f"(accG[mt][nt][3])
                        : "r"(a[mt][0]), "r"(a[mt][1]), "r"(a[mt][2]), "r"(a[mt][3]),
                          "r"(b[nt][0]), "r"(b[nt][1]));
                }
        }

        // end of a 128-wide quant group? apply fp32 per-(n,group) scale
        if ((kt & 3) == 3) {
            const int grp = kt >> 2;
#pragma unroll
            for (int nt = 0; nt < 4; ++nt) {
                const int n = bn + wn * 32 + nt * 8 + tg * 2;
                const float s0 = __ldg(&scales[(size_t)n * NGROUPS + grp]);
                const float s1 = __ldg(&scales[(size_t)(n + 1) * NGROUPS + grp]);
#pragma unroll
                for (int mt = 0; mt < 4; ++mt) {
                    accM[mt][nt][0] += s0 * accG[mt][nt][0];
                    accM[mt][nt][1] += s1 * accG[mt][nt][1];
                    accM[mt][nt][2] += s0 * accG[mt][nt][2];
                    accM[mt][nt][3] += s1 * accG[mt][nt][3];
                    accG[mt][nt][0] = 0.f; accG[mt][nt][1] = 0.f;
                    accG[mt][nt][2] = 0.f; accG[mt][nt][3] = 0.f;
                }
            }
        }
        buf ^= 1;
    }

    // write out (fp32, row-major [TOKENS, NDIM])
#pragma unroll
    for (int mt = 0; mt < 4; ++mt) {
        const int row0 = bm + wm * 64 + mt * 16 + g;
#pragma unroll
        for (int nt = 0; nt < 4; ++nt) {
            const int col = bn + wn * 32 + nt * 8 + tg * 2;
            *(float2*)&out[(size_t)row0 * NDIM + col] =
                make_float2(accM[mt][nt][0], accM[mt][nt][1]);
            *(float2*)&out[(size_t)(row0 + 8) * NDIM + col] =
                make_float2(accM[mt][nt][2], accM[mt][nt][3]);
        }
    }
}

// ---------------------------------------------------------------------------
extern "C" void kernel_launch(void* const* d_in, const int* in_sizes, int n_in,
                              void* d_out, int out_size) {
    const float* x  = (const float*)d_in[0];
    const int*   wp = (const int*)d_in[1];
    const float* ws = (const float*)d_in[2];
    float* out = (float*)d_out;

    convert_x_kernel<<<(TOKENS * (size_t)KDIM / 8) / 256, 256>>>(x);
    dequant_w_kernel<<<(NDIM * (size_t)KDIM / 8) / 256, 256>>>(wp);

    dim3 grid(NDIM / BN, TOKENS / BM);
    gemm_q4_kernel<<<grid, 256>>>(ws, out);
}

// round 3
// speedup vs baseline: 1.7480x; 1.7480x over previous
#include <cuda_runtime.h>
#include <cuda_fp16.h>
#include <cstdint>
#include <cstddef>

#define TOKENS 8192
#define KDIM   4096
#define NDIM   4096
#define NGROUPS 32

// fp16 scratch in device globals (allocation-free rule)
__device__ uint4 g_Xh4[(size_t)TOKENS * KDIM / 8];  // x as half
__device__ uint4 g_Wh4[(size_t)NDIM   * KDIM / 8];  // W as half, scale pre-applied

// ---------------------------------------------------------------------------
// x: fp32 -> fp16
// ---------------------------------------------------------------------------
__global__ void convert_x_kernel(const float* __restrict__ x) {
    size_t idx = (size_t)blockIdx.x * blockDim.x + threadIdx.x;
    const float4* xv = (const float4*)x;
    float4 v0 = xv[2 * idx];
    float4 v1 = xv[2 * idx + 1];
    __half2 h0 = __floats2half2_rn(v0.x, v0.y);
    __half2 h1 = __floats2half2_rn(v0.z, v0.w);
    __half2 h2 = __floats2half2_rn(v1.x, v1.y);
    __half2 h3 = __floats2half2_rn(v1.z, v1.w);
    uint4 o;
    o.x = *reinterpret_cast<unsigned*>(&h0);
    o.y = *reinterpret_cast<unsigned*>(&h1);
    o.z = *reinterpret_cast<unsigned*>(&h2);
    o.w = *reinterpret_cast<unsigned*>(&h3);
    g_Xh4[idx] = o;
}

// ---------------------------------------------------------------------------
// W: packed int4 -> fp16 with per-group scale applied (scale folded into W)
// ---------------------------------------------------------------------------
__global__ void dequant_w_kernel(const int* __restrict__ wp, const float* __restrict__ sc) {
    size_t idx = (size_t)blockIdx.x * blockDim.x + threadIdx.x;
    int4 p = ((const int4*)wp)[idx];
    int n = (int)(idx >> 9);                 // 512 uint4 per row (4096 halves)
    int k = (int)((idx << 3) & (KDIM - 1));  // starting k of the 8 halves
    float s = __ldg(&sc[(size_t)n * NGROUPS + (k >> 7)]);
    __align__(16) __half h[8];
    h[0] = __float2half_rn((float)((p.x & 15) - 8) * s);
    h[1] = __float2half_rn((float)(((p.x >> 4) & 15) - 8) * s);
    h[2] = __float2half_rn((float)((p.y & 15) - 8) * s);
    h[3] = __float2half_rn((float)(((p.y >> 4) & 15) - 8) * s);
    h[4] = __float2half_rn((float)((p.z & 15) - 8) * s);
    h[5] = __float2half_rn((float)(((p.z >> 4) & 15) - 8) * s);
    h[6] = __float2half_rn((float)((p.w & 15) - 8) * s);
    h[7] = __float2half_rn((float)(((p.w >> 4) & 15) - 8) * s);
    g_Wh4[idx] = *reinterpret_cast<uint4*>(h);
}

// ---------------------------------------------------------------------------
// GEMM: out[8192,4096] = Xh @ Wh^T, fp16 mma.sync, fp32 accum
// CTA tile 128x256, BK=64, 3-stage cp.async, 512 threads (16 warps, 2x8)
// Warp tile 64x32, ldmatrix fragment loads.
// ---------------------------------------------------------------------------
#define BM 128
#define BN 256
#define BK 64
#define NSTAGE 3
#define SAS 72                        // smem row stride in halves (64 + 8 pad)
#define A_SMEM_BYTES (BM * SAS * 2)   // 18432
#define B_SMEM_BYTES (BN * SAS * 2)   // 36864
#define STAGE_BYTES (A_SMEM_BYTES + B_SMEM_BYTES)  // 55296
#define SMEM_TOTAL (NSTAGE * STAGE_BYTES)          // 165888

#define CP16(dst, src) asm volatile("cp.async.cg.shared.global [%0], [%1], 16;" :: "r"(dst), "l"(src))
#define LDSM_X4(r0, r1, r2, r3, addr) \
    asm volatile("ldmatrix.sync.aligned.m8n8.x4.shared.b16 {%0,%1,%2,%3}, [%4];" \
        : "=r"(r0), "=r"(r1), "=r"(r2), "=r"(r3) : "r"(addr))

__device__ __forceinline__ uint32_t smem_u32(const void* p) {
    uint32_t a;
    asm("{ .reg .u64 t; cvta.to.shared.u64 t, %1; cvt.u32.u64 %0, t; }" : "=r"(a) : "l"(p));
    return a;
}

__global__ void __launch_bounds__(512, 1)
gemm_hmma_kernel(float* __restrict__ out) {
    extern __shared__ __align__(128) char smem[];
    const uint32_t sb = smem_u32(smem);

    const int tid  = threadIdx.x;
    const int warp = tid >> 5;
    const int lane = tid & 31;
    const int wm = warp >> 3;      // 0..1 -> 64 rows
    const int wn = warp & 7;       // 0..7 -> 32 cols
    const int g  = lane >> 2;      // 0..7
    const int tg = lane & 3;       // 0..3

    const int bm = blockIdx.y * BM;
    const int bn = blockIdx.x * BN;

    const __half* __restrict__ Xh = (const __half*)g_Xh4;
    const __half* __restrict__ Wh = (const __half*)g_Wh4;

    // ldmatrix per-thread smem byte offsets (w/o stage, w/o k-slab offset)
    uint32_t aoff[4];
#pragma unroll
    for (int mt = 0; mt < 4; ++mt)
        aoff[mt] = ((wm * 64 + mt * 16 + (lane & 15)) * SAS + ((lane >> 4) << 3)) * 2;
    uint32_t boff[2];
#pragma unroll
    for (int p = 0; p < 2; ++p)
        boff[p] = A_SMEM_BYTES +
                  ((wn * 32 + p * 16 + (lane & 7) + (((lane >> 4) & 1) << 3)) * SAS +
                   (((lane >> 3) & 1) << 3)) * 2;

    float acc[4][4][4];
#pragma unroll
    for (int i = 0; i < 4; i++)
#pragma unroll
        for (int j = 0; j < 4; j++)
#pragma unroll
            for (int r = 0; r < 4; r++) acc[i][j][r] = 0.f;

    auto load_stage = [&](int slot, int kt) {
        const uint32_t sbase = sb + slot * STAGE_BYTES;
        const int k0 = kt * BK;
        // A: 128 rows x 64 halves = 1024 16B chunks
#pragma unroll
        for (int i = 0; i < 2; ++i) {
            int c = tid + i * 512;
            int row = c >> 3, col = (c & 7) << 3;
            CP16(sbase + (row * SAS + col) * 2,
                 Xh + (size_t)(bm + row) * KDIM + k0 + col);
        }
        // B: 256 rows x 64 halves = 2048 chunks
#pragma unroll
        for (int i = 0; i < 4; ++i) {
            int c = tid + i * 512;
            int row = c >> 3, col = (c & 7) << 3;
            CP16(sbase + A_SMEM_BYTES + (row * SAS + col) * 2,
                 Wh + (size_t)(bn + row) * KDIM + k0 + col);
        }
        asm volatile("cp.async.commit_group;");
    };

    const int NKT = KDIM / BK;   // 64
    load_stage(0, 0);
    load_stage(1, 1);

#pragma unroll 1
    for (int s = 0; s < NKT; ++s) {
        asm volatile("cp.async.wait_group 1;");
        __syncthreads();
        if (s + 2 < NKT) load_stage((s + 2) % NSTAGE, s + 2);

        const uint32_t sbase = sb + (s % NSTAGE) * STAGE_BYTES;
#pragma unroll
        for (int kk = 0; kk < 4; ++kk) {      // 4 x k16 per stage
            const uint32_t kof = kk * 32;     // 16 halves = 32 bytes
            uint32_t a[4][4], b[4][2];
#pragma unroll
            for (int mt = 0; mt < 4; ++mt)
                LDSM_X4(a[mt][0], a[mt][1], a[mt][2], a[mt][3],
                        sbase + aoff[mt] + kof);
#pragma unroll
            for (int p = 0; p < 2; ++p)
                LDSM_X4(b[2 * p][0], b[2 * p][1], b[2 * p + 1][0], b[2 * p + 1][1],
                        sbase + boff[p] + kof);
#pragma unroll
            for (int mt = 0; mt < 4; ++mt)
#pragma unroll
                for (int nt = 0; nt < 4; ++nt) {
                    asm volatile(
                        "mma.sync.aligned.m16n8k16.row.col.f32.f16.f16.f32 "
                        "{%0,%1,%2,%3}, {%4,%5,%6,%7}, {%8,%9}, {%0,%1,%2,%3};"
                        : "+f"(acc[mt][nt][0]), "+f"(acc[mt][nt][1]),
                          "+f"(acc[mt][nt][2]), "+f"(acc[mt][nt][3])
                        : "r"(a[mt][0]), "r"(a[mt][1]), "r"(a[mt][2]), "r"(a[mt][3]),
                          "r"(b[nt][0]), "r"(b[nt][1]));
                }
        }
    }

    // epilogue: direct fp32 stores
#pragma unroll
    for (int mt = 0; mt < 4; ++mt) {
        const int row0 = bm + wm * 64 + mt * 16 + g;
#pragma unroll
        for (int nt = 0; nt < 4; ++nt) {
            const int col = bn + wn * 32 + nt * 8 + tg * 2;
            *(float2*)&out[(size_t)row0 * NDIM + col] =
                make_float2(acc[mt][nt][0], acc[mt][nt][1]);
            *(float2*)&out[(size_t)(row0 + 8) * NDIM + col] =
                make_float2(acc[mt][nt][2], acc[mt][nt][3]);
        }
    }
}

// ---------------------------------------------------------------------------
extern "C" void kernel_launch(void* const* d_in, const int* in_sizes, int n_in,
                              void* d_out, int out_size) {
    const float* x  = (const float*)d_in[0];
    const int*   wp = (const int*)d_in[1];
    const float* ws = (const float*)d_in[2];
    float* out = (float*)d_out;

    convert_x_kernel<<<(TOKENS * (size_t)KDIM / 8) / 256, 256>>>(x);
    dequant_w_kernel<<<(NDIM * (size_t)KDIM / 8) / 256, 256>>>(wp, ws);

    static bool attr_set = false;
    if (!attr_set) {
        cudaFuncSetAttribute(gemm_hmma_kernel,
                             cudaFuncAttributeMaxDynamicSharedMemorySize, SMEM_TOTAL);
        attr_set = true;
    }
    dim3 grid(NDIM / BN, TOKENS / BM);
    gemm_hmma_kernel<<<grid, 512, SMEM_TOTAL>>>(out);
}